// round 5
// baseline (speedup 1.0000x reference)
#include <cuda_runtime.h>

#define IMGW    2048
#define NPATCH  65536
#define NNODES  255
#define NINT    127
#define KK      64
#define DEPTH   7
#define NLEAF   128
#define WSTRIDE 65

__device__ unsigned char g_leaf[NPATCH];
__device__ float g_S[NLEAF * KK];
__device__ float g_cnt[NLEAF];
__device__ float g_W[NINT * KK];
__device__ float g_T[NINT];
__device__ int   g_done = 0;

// ---------------------------------------------------------------------------
// P0: per internal node i, W[i]=n0-n1 and T[i]=(||n0||^2-||n1||^2)/2.
// Descent decision becomes: go right iff dot(x,W) < T.
// ---------------------------------------------------------------------------
__global__ __launch_bounds__(64) void k_prep(const float* __restrict__ nodes)
{
    const int i = blockIdx.x;          // internal node 0..126
    const int k = threadIdx.x;
    __shared__ float r[64];
    const float n0 = nodes[(2 * i + 1) * KK + k];
    const float n1 = nodes[(2 * i + 2) * KK + k];
    g_W[i * KK + k] = n0 - n1;
    r[k] = n0 * n0 - n1 * n1;
    __syncthreads();
#pragma unroll
    for (int off = 32; off > 0; off >>= 1) {
        if (k < off) r[k] += r[k + off];
        __syncthreads();
    }
    if (k == 0) g_T[i] = 0.5f * r[0];
}

// ---------------------------------------------------------------------------
// K1: tree descent, one thread = one 8x8 patch in registers.
// W staged in shared with stride 65 -> bank = (cur+k)%32, conflict-free
// across divergent rows. 7 x 64 LDS+FMA per thread.
// ---------------------------------------------------------------------------
#define SMEM1 ((NINT * WSTRIDE + NINT) * 4)

__global__ __launch_bounds__(128) void k_descent(const float* __restrict__ image,
                                                 float* __restrict__ out_cur)
{
    extern __shared__ float sh[];            // W swizzled
    float* sT = sh + NINT * WSTRIDE;         // thresholds
    for (int i = threadIdx.x; i < NINT * KK; i += 128)
        sh[(i >> 6) * WSTRIDE + (i & 63)] = g_W[i];
    for (int i = threadIdx.x; i < NINT; i += 128)
        sT[i] = g_T[i];
    __syncthreads();

    const int p  = blockIdx.x * 128 + threadIdx.x;
    const int pi = p >> 8;
    const int pj = p & 255;
    const float* base = image + (pi * 8) * IMGW + pj * 8;

    float x[64];
#pragma unroll
    for (int r = 0; r < 8; ++r) {
        float4 v0 = *reinterpret_cast<const float4*>(base + r * IMGW);
        float4 v1 = *reinterpret_cast<const float4*>(base + r * IMGW + 4);
        x[r * 8 + 0] = v0.x; x[r * 8 + 1] = v0.y;
        x[r * 8 + 2] = v0.z; x[r * 8 + 3] = v0.w;
        x[r * 8 + 4] = v1.x; x[r * 8 + 5] = v1.y;
        x[r * 8 + 6] = v1.z; x[r * 8 + 7] = v1.w;
    }

    int cur = 0;                             // internal node index 0..126
#pragma unroll 1
    for (int lvl = 0; lvl < DEPTH; ++lvl) {
        const float* w = sh + cur * WSTRIDE;
        float a0 = 0.f, a1 = 0.f, a2 = 0.f, a3 = 0.f;
#pragma unroll
        for (int k = 0; k < 64; k += 4) {
            a0 = fmaf(x[k + 0], w[k + 0], a0);
            a1 = fmaf(x[k + 1], w[k + 1], a1);
            a2 = fmaf(x[k + 2], w[k + 2], a2);
            a3 = fmaf(x[k + 3], w[k + 3], a3);
        }
        const float dot = (a0 + a1) + (a2 + a3);
        cur = 2 * cur + 1 + ((dot < sT[cur]) ? 1 : 0);  // right iff dot < T
    }
    // cur is now the 0-indexed leaf node id in [127, 254]
    g_leaf[p]  = (unsigned char)(cur - 127);
    out_cur[p] = (float)cur;
}

// ---------------------------------------------------------------------------
// K2: per-leaf bucket sums (atomic-free, deterministic), then the LAST block
// to finish builds the subtree-sum tree in shared and writes out_nodes.
// Telescoped ancestor sums:
//   sum_l lrate[min(lv,cp)]*S[l,:] = lr0*H[root] + sum_t lrate[t-1]*H[anc_t]
// ---------------------------------------------------------------------------
#define SMEM2 (NPATCH * 2 + 512 * 16 + 32 * 4 + 16)

__global__ __launch_bounds__(512) void k_bucket(const float* __restrict__ image,
                                                const float* __restrict__ nodes,
                                                float* __restrict__ out_nodes)
{
    extern __shared__ char smem[];
    unsigned short* list = reinterpret_cast<unsigned short*>(smem);              // 128KB
    float4* red4 = reinterpret_cast<float4*>(smem + NPATCH * 2);                 // 8KB
    int*   wexc  = reinterpret_cast<int*>(smem + NPATCH * 2 + 512 * 16);         // 17 ints

    const int tid  = threadIdx.x;
    const int leaf = blockIdx.x;
    const unsigned lv = (unsigned)leaf * 0x01010101u;
    const uint4* leaf4 = reinterpret_cast<const uint4*>(g_leaf);

    // coalesced count: 8 uint4 per thread, lanes contiguous
    uint4 v[8];
    int c = 0;
#pragma unroll
    for (int j = 0; j < 8; ++j) {
        v[j] = leaf4[j * 512 + tid];
        c += __popc(__vcmpeq4(v[j].x, lv)) + __popc(__vcmpeq4(v[j].y, lv))
           + __popc(__vcmpeq4(v[j].z, lv)) + __popc(__vcmpeq4(v[j].w, lv));
    }
    c >>= 3;

    // warp-shuffle inclusive scan + cross-warp offsets
    const int lane = tid & 31, wid = tid >> 5;
    int incl = c;
#pragma unroll
    for (int off = 1; off < 32; off <<= 1) {
        int n = __shfl_up_sync(0xFFFFFFFFu, incl, off);
        if (lane >= off) incl += n;
    }
    if (lane == 31) wexc[wid] = incl;        // warp totals
    __syncthreads();
    if (tid < 16) {
        int t = wexc[tid];
        int s = t;
#pragma unroll
        for (int off = 1; off < 16; off <<= 1) {
            int n = __shfl_up_sync(0xFFFFu, s, off);
            if (tid >= off) s += n;
        }
        wexc[tid] = s - t;                   // exclusive warp offset
        if (tid == 15) wexc[16] = s;         // grand total
    }
    __syncthreads();
    const int total = wexc[16];
    int pos = wexc[wid] + incl - c;          // global exclusive prefix

    // emission from registers (no re-read of g_leaf)
#pragma unroll
    for (int j = 0; j < 8; ++j) {
#pragma unroll
        for (int word = 0; word < 4; ++word) {
            unsigned wv = (word == 0) ? v[j].x : (word == 1) ? v[j].y
                        : (word == 2) ? v[j].z : v[j].w;
            unsigned cmp = __vcmpeq4(wv, lv);
            if (cmp) {
                const int pb = (j * 512 + tid) * 16 + word * 4;
#pragma unroll
                for (int b = 0; b < 4; ++b)
                    if ((cmp >> (8 * b)) & 1u)
                        list[pos++] = (unsigned short)(pb + b);
            }
        }
    }
    __syncthreads();

    // gather: 32 slots x 16 quads, float4 loads, fixed order -> deterministic
    const int q    = tid & 15;
    const int slot = tid >> 4;
    const int r    = q >> 1;
    const int c4   = (q & 1) * 4;
    float4 acc = make_float4(0.f, 0.f, 0.f, 0.f);
    for (int i = slot; i < total; i += 32) {
        const int p  = list[i];
        const int pi = p >> 8;
        const int pj = p & 255;
        float4 t = *reinterpret_cast<const float4*>(image + (pi * 8 + r) * IMGW + pj * 8 + c4);
        acc.x += t.x; acc.y += t.y; acc.z += t.z; acc.w += t.w;
    }
    red4[tid] = acc;
    __syncthreads();

    if (tid < 16) {
        float4 s = make_float4(0.f, 0.f, 0.f, 0.f);
#pragma unroll
        for (int sl = 0; sl < 32; ++sl) {
            float4 t = red4[sl * 16 + tid];
            s.x += t.x; s.y += t.y; s.z += t.z; s.w += t.w;
        }
        const int k0 = (tid >> 1) * 8 + (tid & 1) * 4;
        *reinterpret_cast<float4*>(g_S + leaf * 64 + k0) = s;
    }
    if (tid == 0) g_cnt[leaf] = (float)total;

    // ---- last-block tail: tree build + node update ----
    __threadfence();                         // publish g_S / g_cnt
    __shared__ int s_last;
    __syncthreads();                         // all stores issued before vote
    if (tid == 0)
        s_last = (atomicAdd(&g_done, 1) == NLEAF - 1) ? 1 : 0;
    __syncthreads();
    if (!s_last) return;
    __threadfence();                         // acquire side

    float* shH = reinterpret_cast<float*>(smem);      // [NNODES*KK] (reuse)
    float* shC = shH + NNODES * KK;                   // [NNODES]

    for (int i = tid; i < NLEAF * KK; i += 512)
        shH[(NINT << 6) + i] = g_S[i];
    if (tid < NLEAF)
        shC[NINT + tid] = g_cnt[tid];
    __syncthreads();

#pragma unroll
    for (int l2 = DEPTH - 1; l2 >= 0; --l2) {
        const int first = (1 << l2) - 1;
        const int n     = 1 << l2;
        for (int e = tid; e < n * KK; e += 512) {
            const int i = first + (e >> 6);
            const int k = e & 63;
            shH[i * KK + k] = shH[(2 * i + 1) * KK + k] + shH[(2 * i + 2) * KK + k];
        }
        if (tid < n) {
            const int i = first + tid;
            shC[i] = shC[2 * i + 1] + shC[2 * i + 2];
        }
        __syncthreads();
    }

    const int g = tid >> 6;                  // 0..7
    const int k = tid & 63;
    const float invP = 1.0f / 65536.0f;
    const float lr0  = 0.3f * __int_as_float(120 << 23);   // 0.3 * 2^-7
#pragma unroll 1
    for (int j = g; j < NNODES; j += 8) {
        const float nv = nodes[j * 64 + k];
        if (j == 0) { out_nodes[k] = nv; continue; }
        const int m  = j + 1;
        const int lvn = 31 - __clz(m);
        float s1 = lr0 * shH[k];
        float sc = lr0 * shC[0];
#pragma unroll 1
        for (int t = 1; t <= lvn; ++t) {
            const int anc = (m >> (lvn - t)) - 1;
            const float lr = 0.3f * __int_as_float((t - 1 + 120) << 23);
            s1 = fmaf(lr, shH[anc * 64 + k], s1);
            sc = fmaf(lr, shC[anc], sc);
        }
        out_nodes[j * 64 + k] = nv + s1 * invP - (sc * invP) * nv;
    }

    if (tid == 0) g_done = 0;                // reset for next graph replay
}

// ---------------------------------------------------------------------------
extern "C" void kernel_launch(void* const* d_in, const int* in_sizes, int n_in,
                              void* d_out, int out_size)
{
    const float* image = (const float*)d_in[0];
    const float* nodes = (const float*)d_in[1];
    float* out       = (float*)d_out;
    float* out_nodes = out;                      // 255*64 floats
    float* out_cur   = out + NNODES * KK;        // 65536 floats

    cudaFuncSetAttribute(k_bucket, cudaFuncAttributeMaxDynamicSharedMemorySize, SMEM2);

    k_prep<<<NINT, 64>>>(nodes);
    k_descent<<<NPATCH / 128, 128, SMEM1>>>(image, out_cur);
    k_bucket<<<NLEAF, 512, SMEM2>>>(image, nodes, out_nodes);
}

// round 6
// speedup vs baseline: 1.3960x; 1.3960x over previous
#include <cuda_runtime.h>

#define IMGW    2048
#define NPATCH  65536
#define NNODES  255
#define NINT    127
#define KK      64
#define DEPTH   7
#define NLEAF   128
#define WSTRIDE 65

__device__ unsigned char g_leaf[NPATCH];
__device__ float g_S[NLEAF * KK];
__device__ float g_cnt[NLEAF];

// ---------------------------------------------------------------------------
// K1: fused prep + tree descent. 128 blocks x 512 threads, 1 patch/thread.
// Each block redundantly builds W[i]=n0-n1 (swizzled stride-65 shared) and
// T[i]=(||n0||^2-||n1||^2)/2 from nodes (L2-hot). Decision: right iff
// dot(x,W) < T  (equivalent to squared-distance compare).
// ---------------------------------------------------------------------------
#define SMEM1 ((NINT * WSTRIDE + NINT) * 4)

__global__ __launch_bounds__(512) void k_descent(const float* __restrict__ image,
                                                 const float* __restrict__ nodes,
                                                 float* __restrict__ out_cur)
{
    extern __shared__ float sh[];            // W swizzled [127*65]
    float* sT = sh + NINT * WSTRIDE;         // thresholds [127]
    const int tid  = threadIdx.x;
    const int lane = tid & 31;
    const int wid  = tid >> 5;               // 0..15

    // W pass: coalesced streaming diff of sibling rows
    for (int e = tid; e < NINT * KK; e += 512) {
        const int i = e >> 6, k = e & 63;
        const float a = nodes[128 * i + 64 + k];
        const float b = nodes[128 * i + 128 + k];
        sh[i * WSTRIDE + k] = a - b;
    }
    // T pass: warp-per-node, same pairing as the old shared-halving reduction
    for (int i = wid; i < NINT; i += 16) {
        const float a0 = nodes[128 * i + 64 + lane];
        const float b0 = nodes[128 * i + 128 + lane];
        const float a1 = nodes[128 * i + 96 + lane];
        const float b1 = nodes[128 * i + 160 + lane];
        float r = (a0 * a0 - b0 * b0) + (a1 * a1 - b1 * b1);   // off=32 step
#pragma unroll
        for (int off = 16; off > 0; off >>= 1)
            r += __shfl_xor_sync(0xFFFFFFFFu, r, off);
        if (lane == 0) sT[i] = 0.5f * r;
    }
    __syncthreads();

    const int p  = blockIdx.x * 512 + tid;
    const int pi = p >> 8;
    const int pj = p & 255;
    const float* base = image + (pi * 8) * IMGW + pj * 8;

    float x[64];
#pragma unroll
    for (int r = 0; r < 8; ++r) {
        float4 v0 = *reinterpret_cast<const float4*>(base + r * IMGW);
        float4 v1 = *reinterpret_cast<const float4*>(base + r * IMGW + 4);
        x[r * 8 + 0] = v0.x; x[r * 8 + 1] = v0.y;
        x[r * 8 + 2] = v0.z; x[r * 8 + 3] = v0.w;
        x[r * 8 + 4] = v1.x; x[r * 8 + 5] = v1.y;
        x[r * 8 + 6] = v1.z; x[r * 8 + 7] = v1.w;
    }

    int cur = 0;                             // internal node index 0..126
#pragma unroll 1
    for (int lvl = 0; lvl < DEPTH; ++lvl) {
        const float* w = sh + cur * WSTRIDE;
        float a0 = 0.f, a1 = 0.f, a2 = 0.f, a3 = 0.f;
#pragma unroll
        for (int k = 0; k < 64; k += 4) {
            a0 = fmaf(x[k + 0], w[k + 0], a0);
            a1 = fmaf(x[k + 1], w[k + 1], a1);
            a2 = fmaf(x[k + 2], w[k + 2], a2);
            a3 = fmaf(x[k + 3], w[k + 3], a3);
        }
        const float dot = (a0 + a1) + (a2 + a3);
        cur = 2 * cur + 1 + ((dot < sT[cur]) ? 1 : 0);  // right iff dot < T
    }
    // cur is now the 0-indexed leaf node id in [127, 254]
    g_leaf[p]  = (unsigned char)(cur - 127);
    out_cur[p] = (float)cur;
}

// ---------------------------------------------------------------------------
// K2: per-leaf bucket sums, atomic-free & deterministic.
// One block per leaf. Coalesced uint4 scan of g_leaf (kept in regs for
// emission), warp-shuffle prefix scan, float4 gather from L2-resident image.
// ---------------------------------------------------------------------------
#define SMEM2 (NPATCH * 2 + 512 * 16 + 32 * 4 + 16)

__global__ __launch_bounds__(512) void k_bucket(const float* __restrict__ image)
{
    extern __shared__ char smem[];
    unsigned short* list = reinterpret_cast<unsigned short*>(smem);              // 128KB
    float4* red4 = reinterpret_cast<float4*>(smem + NPATCH * 2);                 // 8KB
    int*   wexc  = reinterpret_cast<int*>(smem + NPATCH * 2 + 512 * 16);         // 17 ints

    const int tid  = threadIdx.x;
    const int leaf = blockIdx.x;
    const unsigned lv = (unsigned)leaf * 0x01010101u;
    const uint4* leaf4 = reinterpret_cast<const uint4*>(g_leaf);

    // coalesced count: 8 uint4 per thread, lanes contiguous
    uint4 v[8];
    int c = 0;
#pragma unroll
    for (int j = 0; j < 8; ++j) {
        v[j] = leaf4[j * 512 + tid];
        c += __popc(__vcmpeq4(v[j].x, lv)) + __popc(__vcmpeq4(v[j].y, lv))
           + __popc(__vcmpeq4(v[j].z, lv)) + __popc(__vcmpeq4(v[j].w, lv));
    }
    c >>= 3;

    // warp-shuffle inclusive scan + cross-warp offsets
    const int lane = tid & 31, wid = tid >> 5;
    int incl = c;
#pragma unroll
    for (int off = 1; off < 32; off <<= 1) {
        int n = __shfl_up_sync(0xFFFFFFFFu, incl, off);
        if (lane >= off) incl += n;
    }
    if (lane == 31) wexc[wid] = incl;        // warp totals
    __syncthreads();
    if (tid < 16) {
        int t = wexc[tid];
        int s = t;
#pragma unroll
        for (int off = 1; off < 16; off <<= 1) {
            int n = __shfl_up_sync(0xFFFFu, s, off);
            if (tid >= off) s += n;
        }
        wexc[tid] = s - t;                   // exclusive warp offset
        if (tid == 15) wexc[16] = s;         // grand total
    }
    __syncthreads();
    const int total = wexc[16];
    int pos = wexc[wid] + incl - c;          // global exclusive prefix

    // emission from registers (no re-read of g_leaf)
#pragma unroll
    for (int j = 0; j < 8; ++j) {
#pragma unroll
        for (int word = 0; word < 4; ++word) {
            unsigned wv = (word == 0) ? v[j].x : (word == 1) ? v[j].y
                        : (word == 2) ? v[j].z : v[j].w;
            unsigned cmp = __vcmpeq4(wv, lv);
            if (cmp) {
                const int pb = (j * 512 + tid) * 16 + word * 4;
#pragma unroll
                for (int b = 0; b < 4; ++b)
                    if ((cmp >> (8 * b)) & 1u)
                        list[pos++] = (unsigned short)(pb + b);
            }
        }
    }
    __syncthreads();

    // gather: 32 slots x 16 quads, float4 loads, fixed order -> deterministic
    const int q    = tid & 15;
    const int slot = tid >> 4;
    const int r    = q >> 1;
    const int c4   = (q & 1) * 4;
    float4 acc = make_float4(0.f, 0.f, 0.f, 0.f);
    for (int i = slot; i < total; i += 32) {
        const int p  = list[i];
        const int pi = p >> 8;
        const int pj = p & 255;
        float4 t = *reinterpret_cast<const float4*>(image + (pi * 8 + r) * IMGW + pj * 8 + c4);
        acc.x += t.x; acc.y += t.y; acc.z += t.z; acc.w += t.w;
    }
    red4[tid] = acc;
    __syncthreads();

    if (tid < 16) {
        float4 s = make_float4(0.f, 0.f, 0.f, 0.f);
#pragma unroll
        for (int sl = 0; sl < 32; ++sl) {
            float4 t = red4[sl * 16 + tid];
            s.x += t.x; s.y += t.y; s.z += t.z; s.w += t.w;
        }
        const int k0 = (tid >> 1) * 8 + (tid & 1) * 4;
        *reinterpret_cast<float4*>(g_S + leaf * 64 + k0) = s;
    }
    if (tid == 0) g_cnt[leaf] = (float)total;
}

// ---------------------------------------------------------------------------
// K3: fused subtree-tree + node update. 16 blocks x 512 threads.
// Each block redundantly builds H (subtree sums of S, 255x64) + counts in
// shared, then computes 16 output node rows via telescoped ancestor sums:
//   sum_l lrate[min(lv,cp)]*S[l,:] = lr0*H[root] + sum_t lrate[t-1]*H[anc_t]
// (uses lrate[t] = 2*lrate[t-1]).
// ---------------------------------------------------------------------------
#define SMEM3 ((NNODES * KK + NNODES + 1) * 4)

__global__ __launch_bounds__(512) void k_final(const float* __restrict__ nodes,
                                               float* __restrict__ out_nodes)
{
    extern __shared__ float shH[];               // [NNODES*KK]
    float* shC = shH + NNODES * KK;              // [NNODES]
    const int tid = threadIdx.x;

    // leaves: nodes 127..254
    for (int i = tid; i < NLEAF * KK; i += 512)
        shH[(NINT << 6) + i] = g_S[i];
    if (tid < NLEAF)
        shC[NINT + tid] = g_cnt[tid];
    __syncthreads();

    // upward passes
#pragma unroll
    for (int lvl = DEPTH - 1; lvl >= 0; --lvl) {
        const int first = (1 << lvl) - 1;
        const int n     = 1 << lvl;              // nodes at this level
        for (int e = tid; e < n * KK; e += 512) {
            const int i = first + (e >> 6);
            const int k = e & 63;
            shH[i * KK + k] = shH[(2 * i + 1) * KK + k] + shH[(2 * i + 2) * KK + k];
        }
        if (tid < n) {
            const int i = first + tid;
            shC[i] = shC[2 * i + 1] + shC[2 * i + 2];
        }
        __syncthreads();
    }

    // this block handles 16 node rows: j in [blockIdx.x*16, +16)
    const int g = tid >> 6;            // 0..7 node slot within pass
    const int k = tid & 63;
#pragma unroll
    for (int it = 0; it < 2; ++it) {
        const int j = blockIdx.x * 16 + it * 8 + g;
        if (j >= NNODES) continue;
        const float nv = nodes[j * 64 + k];
        if (j == 0) {                  // root is not updated
            out_nodes[k] = nv;
            continue;
        }
        const int m  = j + 1;              // 1-indexed node in [2,255]
        const int lv = 31 - __clz(m);      // level of node (1..7)

        const float lr0 = 0.3f * __int_as_float(120 << 23);  // 0.3 * 2^-7
        float s1 = lr0 * shH[k];           // root term
        float sc = lr0 * shC[0];
#pragma unroll 1
        for (int t = 1; t <= lv; ++t) {
            const int anc = (m >> (lv - t)) - 1;             // 0-indexed ancestor
            const float lr = 0.3f * __int_as_float((t - 1 + 120) << 23);
            s1 = fmaf(lr, shH[anc * 64 + k], s1);
            sc = fmaf(lr, shC[anc], sc);
        }
        const float invP = 1.0f / 65536.0f;
        out_nodes[j * 64 + k] = nv + s1 * invP - (sc * invP) * nv;
    }
}

// ---------------------------------------------------------------------------
extern "C" void kernel_launch(void* const* d_in, const int* in_sizes, int n_in,
                              void* d_out, int out_size)
{
    const float* image = (const float*)d_in[0];
    const float* nodes = (const float*)d_in[1];
    float* out       = (float*)d_out;
    float* out_nodes = out;                      // 255*64 floats
    float* out_cur   = out + NNODES * KK;        // 65536 floats

    cudaFuncSetAttribute(k_bucket, cudaFuncAttributeMaxDynamicSharedMemorySize, SMEM2);
    cudaFuncSetAttribute(k_final,  cudaFuncAttributeMaxDynamicSharedMemorySize, SMEM3);

    k_descent<<<NPATCH / 512, 512, SMEM1>>>(image, nodes, out_cur);
    k_bucket<<<NLEAF, 512, SMEM2>>>(image);
    k_final<<<16, 512, SMEM3>>>(nodes, out_nodes);
}

// round 7
// speedup vs baseline: 1.4113x; 1.0109x over previous
#include <cuda_runtime.h>

#define IMGW    2048
#define NPATCH  65536
#define NNODES  255
#define NINT    127
#define KK      64
#define DEPTH   7
#define NLEAF   128
#define WSTRIDE 66           // row stride; even half at +0, odd half at +33

__device__ unsigned char g_leaf[NPATCH];
__device__ float g_S[NLEAF * KK];
__device__ float g_cnt[NLEAF];

// ---------------------------------------------------------------------------
// K1: fused prep + descent, TWO threads per patch (lane pairs).
// Each block redundantly builds W[i]=n0-n1 and T[i]=(||n0||^2-||n1||^2)/2.
// Decision: right iff dot(x,W) < T. Lane parity splits the 64-dim dot;
// halves combined with shfl_xor in canonical h0+h1 order (pair-consistent).
// ---------------------------------------------------------------------------
#define SMEM1 ((NINT * WSTRIDE + NINT) * 4)

__global__ __launch_bounds__(512) void k_descent(const float* __restrict__ image,
                                                 const float* __restrict__ nodes,
                                                 float* __restrict__ out_cur)
{
    extern __shared__ float sh[];            // W [127*66], halves at +0 / +33
    float* sT = sh + NINT * WSTRIDE;         // thresholds [127]
    const int tid  = threadIdx.x;
    const int lane = tid & 31;
    const int wid  = tid >> 5;               // 0..15

    // W pass: element k of node i -> sh[i*66 + k + (k>=32)]
    for (int e = tid; e < NINT * KK; e += 512) {
        const int i = e >> 6, k = e & 63;
        const float a = nodes[128 * i + 64 + k];
        const float b = nodes[128 * i + 128 + k];
        sh[i * WSTRIDE + k + (k >> 5)] = a - b;
    }
    // T pass: warp-per-node, same butterfly pairing as before
    for (int i = wid; i < NINT; i += 16) {
        const float a0 = nodes[128 * i + 64 + lane];
        const float b0 = nodes[128 * i + 128 + lane];
        const float a1 = nodes[128 * i + 96 + lane];
        const float b1 = nodes[128 * i + 160 + lane];
        float r = (a0 * a0 - b0 * b0) + (a1 * a1 - b1 * b1);
#pragma unroll
        for (int off = 16; off > 0; off >>= 1)
            r += __shfl_xor_sync(0xFFFFFFFFu, r, off);
        if (lane == 0) sT[i] = 0.5f * r;
    }
    __syncthreads();

    const int parity = tid & 1;
    const int p  = blockIdx.x * 256 + (tid >> 1);   // patch id
    const int pi = p >> 8;
    const int pj = p & 255;
    // parity 0 -> rows 0..3 (elems 0..31); parity 1 -> rows 4..7 (elems 32..63)
    const float* base = image + (pi * 8 + parity * 4) * IMGW + pj * 8;

    float x[32];
#pragma unroll
    for (int r = 0; r < 4; ++r) {
        float4 v0 = *reinterpret_cast<const float4*>(base + r * IMGW);
        float4 v1 = *reinterpret_cast<const float4*>(base + r * IMGW + 4);
        x[r * 8 + 0] = v0.x; x[r * 8 + 1] = v0.y;
        x[r * 8 + 2] = v0.z; x[r * 8 + 3] = v0.w;
        x[r * 8 + 4] = v1.x; x[r * 8 + 5] = v1.y;
        x[r * 8 + 6] = v1.z; x[r * 8 + 7] = v1.w;
    }

    const float* wbase = sh + parity * 33;
    int cur = 0;                             // internal node index 0..126
#pragma unroll 1
    for (int lvl = 0; lvl < DEPTH; ++lvl) {
        const float* w = wbase + cur * WSTRIDE;
        float a0 = 0.f, a1 = 0.f, a2 = 0.f, a3 = 0.f;
#pragma unroll
        for (int k = 0; k < 32; k += 4) {
            a0 = fmaf(x[k + 0], w[k + 0], a0);
            a1 = fmaf(x[k + 1], w[k + 1], a1);
            a2 = fmaf(x[k + 2], w[k + 2], a2);
            a3 = fmaf(x[k + 3], w[k + 3], a3);
        }
        const float mine  = (a0 + a1) + (a2 + a3);
        const float other = __shfl_xor_sync(0xFFFFFFFFu, mine, 1);
        const float h0 = parity ? other : mine;
        const float h1 = parity ? mine  : other;
        const float dot = h0 + h1;           // identical on both lanes
        cur = 2 * cur + 1 + ((dot < sT[cur]) ? 1 : 0);
    }
    // cur is the 0-indexed leaf node id in [127, 254]
    if (parity == 0) {
        g_leaf[p]  = (unsigned char)(cur - 127);
        out_cur[p] = (float)cur;
    }
}

// ---------------------------------------------------------------------------
// K2: per-leaf bucket sums, atomic-free & deterministic.
// One block per leaf. Coalesced uint4 scan of g_leaf (kept in regs for
// emission), warp-shuffle prefix scan, float4 gather from L2-resident image.
// ---------------------------------------------------------------------------
#define SMEM2 (NPATCH * 2 + 512 * 16 + 32 * 4 + 16)

__global__ __launch_bounds__(512) void k_bucket(const float* __restrict__ image)
{
    extern __shared__ char smem[];
    unsigned short* list = reinterpret_cast<unsigned short*>(smem);              // 128KB
    float4* red4 = reinterpret_cast<float4*>(smem + NPATCH * 2);                 // 8KB
    int*   wexc  = reinterpret_cast<int*>(smem + NPATCH * 2 + 512 * 16);         // 17 ints

    const int tid  = threadIdx.x;
    const int leaf = blockIdx.x;
    const unsigned lv = (unsigned)leaf * 0x01010101u;
    const uint4* leaf4 = reinterpret_cast<const uint4*>(g_leaf);

    // coalesced count: 8 uint4 per thread, lanes contiguous
    uint4 v[8];
    int c = 0;
#pragma unroll
    for (int j = 0; j < 8; ++j) {
        v[j] = leaf4[j * 512 + tid];
        c += __popc(__vcmpeq4(v[j].x, lv)) + __popc(__vcmpeq4(v[j].y, lv))
           + __popc(__vcmpeq4(v[j].z, lv)) + __popc(__vcmpeq4(v[j].w, lv));
    }
    c >>= 3;

    // warp-shuffle inclusive scan + cross-warp offsets
    const int lane = tid & 31, wid = tid >> 5;
    int incl = c;
#pragma unroll
    for (int off = 1; off < 32; off <<= 1) {
        int n = __shfl_up_sync(0xFFFFFFFFu, incl, off);
        if (lane >= off) incl += n;
    }
    if (lane == 31) wexc[wid] = incl;        // warp totals
    __syncthreads();
    if (tid < 16) {
        int t = wexc[tid];
        int s = t;
#pragma unroll
        for (int off = 1; off < 16; off <<= 1) {
            int n = __shfl_up_sync(0xFFFFu, s, off);
            if (tid >= off) s += n;
        }
        wexc[tid] = s - t;                   // exclusive warp offset
        if (tid == 15) wexc[16] = s;         // grand total
    }
    __syncthreads();
    const int total = wexc[16];
    int pos = wexc[wid] + incl - c;          // global exclusive prefix

    // emission from registers (no re-read of g_leaf)
#pragma unroll
    for (int j = 0; j < 8; ++j) {
#pragma unroll
        for (int word = 0; word < 4; ++word) {
            unsigned wv = (word == 0) ? v[j].x : (word == 1) ? v[j].y
                        : (word == 2) ? v[j].z : v[j].w;
            unsigned cmp = __vcmpeq4(wv, lv);
            if (cmp) {
                const int pb = (j * 512 + tid) * 16 + word * 4;
#pragma unroll
                for (int b = 0; b < 4; ++b)
                    if ((cmp >> (8 * b)) & 1u)
                        list[pos++] = (unsigned short)(pb + b);
            }
        }
    }
    __syncthreads();

    // gather: 32 slots x 16 quads, float4 loads, fixed order -> deterministic
    const int q    = tid & 15;
    const int slot = tid >> 4;
    const int r    = q >> 1;
    const int c4   = (q & 1) * 4;
    float4 acc = make_float4(0.f, 0.f, 0.f, 0.f);
    for (int i = slot; i < total; i += 32) {
        const int p  = list[i];
        const int pi = p >> 8;
        const int pj = p & 255;
        float4 t = *reinterpret_cast<const float4*>(image + (pi * 8 + r) * IMGW + pj * 8 + c4);
        acc.x += t.x; acc.y += t.y; acc.z += t.z; acc.w += t.w;
    }
    red4[tid] = acc;
    __syncthreads();

    if (tid < 16) {
        float4 s = make_float4(0.f, 0.f, 0.f, 0.f);
#pragma unroll
        for (int sl = 0; sl < 32; ++sl) {
            float4 t = red4[sl * 16 + tid];
            s.x += t.x; s.y += t.y; s.z += t.z; s.w += t.w;
        }
        const int k0 = (tid >> 1) * 8 + (tid & 1) * 4;
        *reinterpret_cast<float4*>(g_S + leaf * 64 + k0) = s;
    }
    if (tid == 0) g_cnt[leaf] = (float)total;
}

// ---------------------------------------------------------------------------
// K3: fused subtree-tree + node update. 128 blocks x 512 threads (wide grid
// on purpose — small-grid tail kernels are empirically penalized ~3x).
// Each block redundantly builds H (subtree sums of S) + counts in shared,
// then emits 2 node rows via telescoped ancestor sums:
//   sum_l lrate[min(lv,cp)]*S[l,:] = lr0*H[root] + sum_t lrate[t-1]*H[anc_t]
// ---------------------------------------------------------------------------
#define SMEM3 ((NNODES * KK + NNODES + 1) * 4)

__global__ __launch_bounds__(512) void k_final(const float* __restrict__ nodes,
                                               float* __restrict__ out_nodes)
{
    extern __shared__ float shH[];               // [NNODES*KK]
    float* shC = shH + NNODES * KK;              // [NNODES]
    const int tid = threadIdx.x;

    // leaves: nodes 127..254
    for (int i = tid; i < NLEAF * KK; i += 512)
        shH[(NINT << 6) + i] = g_S[i];
    if (tid < NLEAF)
        shC[NINT + tid] = g_cnt[tid];
    __syncthreads();

    // upward passes
#pragma unroll
    for (int lvl = DEPTH - 1; lvl >= 0; --lvl) {
        const int first = (1 << lvl) - 1;
        const int n     = 1 << lvl;              // nodes at this level
        for (int e = tid; e < n * KK; e += 512) {
            const int i = first + (e >> 6);
            const int k = e & 63;
            shH[i * KK + k] = shH[(2 * i + 1) * KK + k] + shH[(2 * i + 2) * KK + k];
        }
        if (tid < n) {
            const int i = first + tid;
            shC[i] = shC[2 * i + 1] + shC[2 * i + 2];
        }
        __syncthreads();
    }

    // this block emits node rows 2b and 2b+1
    const int g = tid >> 6;            // 0..7
    const int k = tid & 63;
    if (g >= 2) return;
    const int j = blockIdx.x * 2 + g;
    if (j >= NNODES) return;
    const float nv = nodes[j * 64 + k];
    if (j == 0) {                      // root is not updated
        out_nodes[k] = nv;
        return;
    }
    const int m  = j + 1;              // 1-indexed node in [2,255]
    const int lv = 31 - __clz(m);      // level of node (1..7)

    const float lr0 = 0.3f * __int_as_float(120 << 23);  // 0.3 * 2^-7
    float s1 = lr0 * shH[k];           // root term
    float sc = lr0 * shC[0];
#pragma unroll 1
    for (int t = 1; t <= lv; ++t) {
        const int anc = (m >> (lv - t)) - 1;             // 0-indexed ancestor
        const float lr = 0.3f * __int_as_float((t - 1 + 120) << 23);
        s1 = fmaf(lr, shH[anc * 64 + k], s1);
        sc = fmaf(lr, shC[anc], sc);
    }
    const float invP = 1.0f / 65536.0f;
    out_nodes[j * 64 + k] = nv + s1 * invP - (sc * invP) * nv;
}

// ---------------------------------------------------------------------------
extern "C" void kernel_launch(void* const* d_in, const int* in_sizes, int n_in,
                              void* d_out, int out_size)
{
    const float* image = (const float*)d_in[0];
    const float* nodes = (const float*)d_in[1];
    float* out       = (float*)d_out;
    float* out_nodes = out;                      // 255*64 floats
    float* out_cur   = out + NNODES * KK;        // 65536 floats

    cudaFuncSetAttribute(k_bucket, cudaFuncAttributeMaxDynamicSharedMemorySize, SMEM2);
    cudaFuncSetAttribute(k_final,  cudaFuncAttributeMaxDynamicSharedMemorySize, SMEM3);

    k_descent<<<NPATCH / 256, 512, SMEM1>>>(image, nodes, out_cur);
    k_bucket<<<NLEAF, 512, SMEM2>>>(image);
    k_final<<<128, 512, SMEM3>>>(nodes, out_nodes);
}